// round 2
// baseline (speedup 1.0000x reference)
#include <cuda_runtime.h>
#include <math.h>

// ---------------------------------------------------------------------------
// Problem constants: B=8, S=1024, D=512, H=8, dh=64, MAX_POS=128
// inputs: 0:x [8,1024,512] f32, 1:mask [8,1024] i32, 2:W_in [512,1536],
//         3:b_in [1536], 4:W_out [512,512], 5:b_out [512],
//         6:pos_K [257,64], 7:pos_V [257,64]
// output: [8,1024,512] f32
// ---------------------------------------------------------------------------

static __device__ float g_Q[8 * 8 * 1024 * 64];   // [b,h,s,d], pre-scaled by 1/8
static __device__ float g_K[8 * 8 * 1024 * 64];
static __device__ float g_V[8 * 8 * 1024 * 64];
static __device__ float g_O[8192 * 512];          // [b,s,h*64+d]

// ======================= Kernel 1: qkv GEMM + scatter ======================
// C[m,n] = x[m,:] @ W_in[:,n] + b_in[n];   m in [0,8192), n in [0,1536)
// scatter: part=n/512 (Q,K,V), h=(n%512)/64, d=n%64; Q scaled by 0.125
__global__ __launch_bounds__(256, 2)
void qkv_gemm_kernel(const float* __restrict__ A,
                     const float* __restrict__ Wv,
                     const float* __restrict__ bias)
{
    __shared__ float As[16][132];   // As[k][m] (transposed)
    __shared__ float Bs[16][132];   // Bs[k][n]
    const int t  = threadIdx.x;
    const int tx = t & 15, ty = t >> 4;
    const int n0 = blockIdx.x * 128;
    const int m0 = blockIdx.y * 128;

    float acc[8][8];
#pragma unroll
    for (int i = 0; i < 8; i++)
#pragma unroll
        for (int j = 0; j < 8; j++) acc[i][j] = 0.f;

    for (int k0 = 0; k0 < 512; k0 += 16) {
        __syncthreads();
#pragma unroll
        for (int c = 0; c < 2; c++) {
            int i0 = t + c * 256;                 // 0..511
            int m = i0 >> 2, kv = i0 & 3;
            float4 v = *(const float4*)(A + (size_t)(m0 + m) * 512 + k0 + kv * 4);
            As[kv * 4 + 0][m] = v.x; As[kv * 4 + 1][m] = v.y;
            As[kv * 4 + 2][m] = v.z; As[kv * 4 + 3][m] = v.w;
        }
#pragma unroll
        for (int c = 0; c < 2; c++) {
            int i0 = t + c * 256;
            int k = i0 >> 5, nv = i0 & 31;
            *(float4*)&Bs[k][nv * 4] =
                *(const float4*)(Wv + (size_t)(k0 + k) * 1536 + n0 + nv * 4);
        }
        __syncthreads();
#pragma unroll
        for (int kk = 0; kk < 16; kk++) {
            float a_[8], b_[8];
            *(float4*)&a_[0] = *(float4*)&As[kk][ty * 8];
            *(float4*)&a_[4] = *(float4*)&As[kk][ty * 8 + 4];
            *(float4*)&b_[0] = *(float4*)&Bs[kk][tx * 8];
            *(float4*)&b_[4] = *(float4*)&Bs[kk][tx * 8 + 4];
#pragma unroll
            for (int i = 0; i < 8; i++)
#pragma unroll
                for (int j = 0; j < 8; j++)
                    acc[i][j] += a_[i] * b_[j];
        }
    }

#pragma unroll
    for (int i = 0; i < 8; i++) {
        int m = m0 + ty * 8 + i;
        int b = m >> 10, s = m & 1023;
#pragma unroll
        for (int jj = 0; jj < 2; jj++) {
            int n = n0 + tx * 8 + jj * 4;     // 4 consecutive cols, same h-block
            int part = n >> 9;
            int r = n & 511;
            int h = r >> 6, d = r & 63;
            float sc = (part == 0) ? 0.125f : 1.f;
            float4 v;
            v.x = (acc[i][jj * 4 + 0] + bias[n + 0]) * sc;
            v.y = (acc[i][jj * 4 + 1] + bias[n + 1]) * sc;
            v.z = (acc[i][jj * 4 + 2] + bias[n + 2]) * sc;
            v.w = (acc[i][jj * 4 + 3] + bias[n + 3]) * sc;
            float* dst = (part == 0) ? g_Q : (part == 1) ? g_K : g_V;
            *(float4*)(dst + ((size_t)(b * 8 + h) * 1024 + s) * 64 + d) = v;
        }
    }
}

// ======================= Kernel 2: fused attention =========================
// grid = (16 q-tiles, 64 bh), block = 256 (16x16), Tq=Tk=64, 4x4 microtiles.
// Dynamic smem layout (floats):
//   Qt [64][72]  : Q^T tile, Qt[d][q]
//   Kt [64][72]  : K^T / posK^T / posV tile (reused)
//   Vs [64][72]  : V tile, Vs[k][d]
//   Pt [64][72]  : P^T tile, Pt[k][q]
//   Qp [64][260] : Qp[q][r], r in [0,257)
//   Ap [64][260] : Ap[q][r] accumulator (flash-rescaled)
#define SM_QT 0
#define SM_KT 4608
#define SM_VS 9216
#define SM_PT 13824
#define SM_QP 18432
#define SM_AP 35072
#define ATTN_SMEM_BYTES ((35072 + 64 * 260) * 4)   // 206848 B

__global__ __launch_bounds__(256)
void attn_kernel(const int* __restrict__ mask,
                 const float* __restrict__ posK,
                 const float* __restrict__ posV)
{
    extern __shared__ float smf[];
    float* Qt = smf + SM_QT;
    float* Kt = smf + SM_KT;
    float* Vs = smf + SM_VS;
    float* Pt = smf + SM_PT;
    float* Qp = smf + SM_QP;
    float* Ap = smf + SM_AP;

    const int t  = threadIdx.x;
    const int tx = t & 15, ty = t >> 4;
    const int q0 = blockIdx.x * 64;
    const int bh = blockIdx.y;
    const int bb = bh >> 3, hh = bh & 7;

    const float* Qb = g_Q + (size_t)bh * 65536;
    const float* Kb = g_K + (size_t)bh * 65536;
    const float* Vb = g_V + (size_t)bh * 65536;

    // load Q tile transposed; zero Ap
    for (int i = t; i < 4096; i += 256) {
        int q = i >> 6, d = i & 63;
        Qt[d * 72 + q] = Qb[(size_t)(q0 + q) * 64 + d];
    }
    for (int i = t; i < 64 * 260; i += 256) Ap[i] = 0.f;
    __syncthreads();

    // ---- Qp[q][r] = Q[q,:] . posK[r,:]  (5 r-tiles of 64) ----
    for (int rt = 0; rt < 5; rt++) {
        int r0 = rt * 64;
        for (int i = t; i < 4096; i += 256) {
            int r = i >> 6, d = i & 63;
            Kt[d * 72 + r] = (r0 + r < 257) ? posK[(r0 + r) * 64 + d] : 0.f;
        }
        __syncthreads();
        float acc[4][4];
#pragma unroll
        for (int i = 0; i < 4; i++)
#pragma unroll
            for (int j = 0; j < 4; j++) acc[i][j] = 0.f;
#pragma unroll 8
        for (int d = 0; d < 64; d++) {
            float4 a = *(float4*)&Qt[d * 72 + ty * 4];
            float4 b = *(float4*)&Kt[d * 72 + tx * 4];
            float a_[4] = {a.x, a.y, a.z, a.w};
            float b_[4] = {b.x, b.y, b.z, b.w};
#pragma unroll
            for (int i = 0; i < 4; i++)
#pragma unroll
                for (int j = 0; j < 4; j++) acc[i][j] += a_[i] * b_[j];
        }
#pragma unroll
        for (int i = 0; i < 4; i++)
#pragma unroll
            for (int j = 0; j < 4; j++) {
                int r = r0 + tx * 4 + j;
                if (r < 257) Qp[(ty * 4 + i) * 260 + r] = acc[i][j];
            }
        __syncthreads();
    }

    float mrow[4], lrow[4], o1[4][4];
#pragma unroll
    for (int i = 0; i < 4; i++) {
        mrow[i] = -1e30f; lrow[i] = 0.f;
#pragma unroll
        for (int j = 0; j < 4; j++) o1[i][j] = 0.f;
    }

    // ---- main loop over 16 k-tiles ----
    for (int kt = 0; kt < 16; kt++) {
        int k0 = kt * 64;
        __syncthreads();   // protect Kt/Vs/Pt from previous iteration
        for (int i = t; i < 4096; i += 256) {
            int k = i >> 6, d = i & 63;
            float kvv = Kb[(size_t)(k0 + k) * 64 + d];
            float vvv = Vb[(size_t)(k0 + k) * 64 + d];
            Kt[d * 72 + k] = kvv;
            Vs[k * 72 + d] = vvv;
        }
        __syncthreads();

        // S1 = Q K^T
        float sv[4][4];
#pragma unroll
        for (int i = 0; i < 4; i++)
#pragma unroll
            for (int j = 0; j < 4; j++) sv[i][j] = 0.f;
#pragma unroll 8
        for (int d = 0; d < 64; d++) {
            float4 a = *(float4*)&Qt[d * 72 + ty * 4];
            float4 b = *(float4*)&Kt[d * 72 + tx * 4];
            float a_[4] = {a.x, a.y, a.z, a.w};
            float b_[4] = {b.x, b.y, b.z, b.w};
#pragma unroll
            for (int i = 0; i < 4; i++)
#pragma unroll
                for (int j = 0; j < 4; j++) sv[i][j] += a_[i] * b_[j];
        }

        int mk[4];
#pragma unroll
        for (int j = 0; j < 4; j++) mk[j] = mask[bb * 1024 + k0 + tx * 4 + j];

        float scl[4];
#pragma unroll
        for (int i = 0; i < 4; i++) {
            int q = q0 + ty * 4 + i;
#pragma unroll
            for (int j = 0; j < 4; j++) {
                int k = k0 + tx * 4 + j;
                int rr = k - q;
                rr = (rr < -128) ? -128 : ((rr > 128) ? 128 : rr);
                float val = sv[i][j] + Qp[(ty * 4 + i) * 260 + rr + 128];
                sv[i][j] = (mk[j] == 0) ? -1e30f : val;
            }
            float mx = fmaxf(fmaxf(sv[i][0], sv[i][1]), fmaxf(sv[i][2], sv[i][3]));
#pragma unroll
            for (int o = 8; o >= 1; o >>= 1)
                mx = fmaxf(mx, __shfl_xor_sync(0xffffffffu, mx, o));
            float mnew = fmaxf(mrow[i], mx);
            float sc = __expf(mrow[i] - mnew);
            mrow[i] = mnew;
            scl[i] = sc;
            float sum = 0.f;
#pragma unroll
            for (int j = 0; j < 4; j++) {
                sv[i][j] = __expf(sv[i][j] - mnew);
                sum += sv[i][j];
            }
#pragma unroll
            for (int o = 8; o >= 1; o >>= 1)
                sum += __shfl_xor_sync(0xffffffffu, sum, o);
            lrow[i] = lrow[i] * sc + sum;
#pragma unroll
            for (int j = 0; j < 4; j++) o1[i][j] *= sc;
        }

        // ---- Ap rescale + accumulate (row-group private, no atomics needed
        //      in the unclipped band; clip bins shuffle-reduced) ----
#pragma unroll
        for (int i = 0; i < 4; i++) {
            float* row = Ap + (ty * 4 + i) * 260;
            float sc = scl[i];
            for (int c = tx; c < 257; c += 16) row[c] *= sc;
        }
        __syncwarp();
#pragma unroll
        for (int i = 0; i < 4; i++) {
            int q = q0 + ty * 4 + i;
            float* row = Ap + (ty * 4 + i) * 260;
            float s0 = 0.f, s256 = 0.f;
#pragma unroll
            for (int j = 0; j < 4; j++) {
                int rr = (k0 + tx * 4 + j) - q;
                if (rr <= -128)      s0   += sv[i][j];
                else if (rr >= 128)  s256 += sv[i][j];
                else                 row[rr + 128] += sv[i][j];
            }
#pragma unroll
            for (int o = 8; o >= 1; o >>= 1) {
                s0   += __shfl_xor_sync(0xffffffffu, s0, o);
                s256 += __shfl_xor_sync(0xffffffffu, s256, o);
            }
            if (tx == 0) { row[0] += s0; row[256] += s256; }
        }

        // P -> smem (transposed), then O1 += P @ V
#pragma unroll
        for (int i = 0; i < 4; i++)
#pragma unroll
            for (int j = 0; j < 4; j++)
                Pt[(tx * 4 + j) * 72 + ty * 4 + i] = sv[i][j];
        __syncthreads();
#pragma unroll 8
        for (int kk = 0; kk < 64; kk++) {
            float4 a = *(float4*)&Pt[kk * 72 + ty * 4];
            float4 b = *(float4*)&Vs[kk * 72 + tx * 4];
            float a_[4] = {a.x, a.y, a.z, a.w};
            float b_[4] = {b.x, b.y, b.z, b.w};
#pragma unroll
            for (int i = 0; i < 4; i++)
#pragma unroll
                for (int j = 0; j < 4; j++) o1[i][j] += a_[i] * b_[j];
        }
    }

    // ---- O2 = Ap @ posV ----
    float o2[4][4];
#pragma unroll
    for (int i = 0; i < 4; i++)
#pragma unroll
        for (int j = 0; j < 4; j++) o2[i][j] = 0.f;

    for (int rt = 0; rt < 5; rt++) {
        int r0 = rt * 64;
        int rlen = (r0 + 64 <= 257) ? 64 : (257 - r0);
        __syncthreads();
        for (int i = t; i < 4096; i += 256) {
            int r = i >> 6, d = i & 63;
            Kt[r * 72 + d] = (r0 + r < 257) ? posV[(r0 + r) * 64 + d] : 0.f;
        }
        __syncthreads();
        for (int kk = 0; kk < rlen; kk++) {
            float4 b = *(float4*)&Kt[kk * 72 + tx * 4];
#pragma unroll
            for (int i = 0; i < 4; i++) {
                float a = Ap[(ty * 4 + i) * 260 + r0 + kk];
                o2[i][0] += a * b.x; o2[i][1] += a * b.y;
                o2[i][2] += a * b.z; o2[i][3] += a * b.w;
            }
        }
    }

    // ---- write O ([b, s, h*64+d], normalized) ----
#pragma unroll
    for (int i = 0; i < 4; i++) {
        int q = q0 + ty * 4 + i;
        float inv = 1.f / lrow[i];
        float4 v;
        v.x = (o1[i][0] + o2[i][0]) * inv;
        v.y = (o1[i][1] + o2[i][1]) * inv;
        v.z = (o1[i][2] + o2[i][2]) * inv;
        v.w = (o1[i][3] + o2[i][3]) * inv;
        *(float4*)(g_O + ((size_t)bb * 1024 + q) * 512 + hh * 64 + tx * 4) = v;
    }
}

// ======================= Kernel 3: output GEMM =============================
// out[m,n] = g_O[m,:] @ W_out[:,n] + b_out[n];  M=8192, N=512, K=512
__global__ __launch_bounds__(256, 2)
void out_gemm_kernel(const float* __restrict__ Wv,
                     const float* __restrict__ bias,
                     float* __restrict__ C)
{
    __shared__ float As[16][132];
    __shared__ float Bs[16][132];
    const int t  = threadIdx.x;
    const int tx = t & 15, ty = t >> 4;
    const int n0 = blockIdx.x * 128;
    const int m0 = blockIdx.y * 128;

    float acc[8][8];
#pragma unroll
    for (int i = 0; i < 8; i++)
#pragma unroll
        for (int j = 0; j < 8; j++) acc[i][j] = 0.f;

    for (int k0 = 0; k0 < 512; k0 += 16) {
        __syncthreads();
#pragma unroll
        for (int c = 0; c < 2; c++) {
            int i0 = t + c * 256;
            int m = i0 >> 2, kv = i0 & 3;
            float4 v = *(const float4*)(g_O + (size_t)(m0 + m) * 512 + k0 + kv * 4);
            As[kv * 4 + 0][m] = v.x; As[kv * 4 + 1][m] = v.y;
            As[kv * 4 + 2][m] = v.z; As[kv * 4 + 3][m] = v.w;
        }
#pragma unroll
        for (int c = 0; c < 2; c++) {
            int i0 = t + c * 256;
            int k = i0 >> 5, nv = i0 & 31;
            *(float4*)&Bs[k][nv * 4] =
                *(const float4*)(Wv + (size_t)(k0 + k) * 512 + n0 + nv * 4);
        }
        __syncthreads();
#pragma unroll
        for (int kk = 0; kk < 16; kk++) {
            float a_[8], b_[8];
            *(float4*)&a_[0] = *(float4*)&As[kk][ty * 8];
            *(float4*)&a_[4] = *(float4*)&As[kk][ty * 8 + 4];
            *(float4*)&b_[0] = *(float4*)&Bs[kk][tx * 8];
            *(float4*)&b_[4] = *(float4*)&Bs[kk][tx * 8 + 4];
#pragma unroll
            for (int i = 0; i < 8; i++)
#pragma unroll
                for (int j = 0; j < 8; j++)
                    acc[i][j] += a_[i] * b_[j];
        }
    }

#pragma unroll
    for (int i = 0; i < 8; i++) {
        int m = m0 + ty * 8 + i;
#pragma unroll
        for (int jj = 0; jj < 2; jj++) {
            int n = n0 + tx * 8 + jj * 4;
            float4 v;
            v.x = acc[i][jj * 4 + 0] + bias[n + 0];
            v.y = acc[i][jj * 4 + 1] + bias[n + 1];
            v.z = acc[i][jj * 4 + 2] + bias[n + 2];
            v.w = acc[i][jj * 4 + 3] + bias[n + 3];
            *(float4*)(C + (size_t)m * 512 + n) = v;
        }
    }
}

// ============================== launcher ===================================
extern "C" void kernel_launch(void* const* d_in, const int* in_sizes, int n_in,
                              void* d_out, int out_size)
{
    const float* x     = (const float*)d_in[0];
    const int*   mask  = (const int*)  d_in[1];
    const float* W_in  = (const float*)d_in[2];
    const float* b_in  = (const float*)d_in[3];
    const float* W_out = (const float*)d_in[4];
    const float* b_out = (const float*)d_in[5];
    const float* posK  = (const float*)d_in[6];
    const float* posV  = (const float*)d_in[7];
    float* out = (float*)d_out;
    (void)in_sizes; (void)n_in; (void)out_size;

    cudaFuncSetAttribute(attn_kernel,
                         cudaFuncAttributeMaxDynamicSharedMemorySize,
                         ATTN_SMEM_BYTES);

    qkv_gemm_kernel<<<dim3(12, 64), 256>>>(x, W_in, b_in);
    attn_kernel<<<dim3(16, 64), 256, ATTN_SMEM_BYTES>>>(mask, posK, posV);
    out_gemm_kernel<<<dim3(4, 64), 256>>>(W_out, b_out, out);
}

// round 3
// speedup vs baseline: 1.0426x; 1.0426x over previous
#include <cuda_runtime.h>
#include <cuda_bf16.h>
#include <math.h>

typedef unsigned int u32;

// ---------------------------------------------------------------------------
// Problem: B=8, S=1024, D=512, H=8, dh=64, MAX_POS=128
// inputs: 0:x f32[8,1024,512], 1:mask i32[8,1024], 2:W_in[512,1536],
//         3:b_in[1536], 4:W_out[512,512], 5:b_out[512],
//         6:pos_K[257,64], 7:pos_V[257,64];  output f32[8,1024,512]
// ---------------------------------------------------------------------------

// split-bf16 Q/K/V, layout [bh][s][d]; Q pre-scaled by 1/8
static __device__ __nv_bfloat16 g_Qh[8*8*1024*64];
static __device__ __nv_bfloat16 g_Ql[8*8*1024*64];
static __device__ __nv_bfloat16 g_Kh[8*8*1024*64];
static __device__ __nv_bfloat16 g_Kl[8*8*1024*64];
static __device__ __nv_bfloat16 g_Vh[8*8*1024*64];
static __device__ __nv_bfloat16 g_Vl[8*8*1024*64];
// V transposed: [bh][d][s]
static __device__ __nv_bfloat16 g_Vth[8*8*64*1024];
static __device__ __nv_bfloat16 g_Vtl[8*8*64*1024];
static __device__ float g_O[8192*512];            // [b,s,h*64+d]

// ---------------------------- helpers --------------------------------------
__device__ __forceinline__ u32 pack2(__nv_bfloat16 x, __nv_bfloat16 y){
    __nv_bfloat162 t; t.x = x; t.y = y;
    return *reinterpret_cast<u32*>(&t);
}
__device__ __forceinline__ void split_bf(float v, __nv_bfloat16& h, __nv_bfloat16& l){
    h = __float2bfloat16(v);
    l = __float2bfloat16(v - __bfloat162float(h));
}
__device__ __forceinline__ void mma16816(float c[4], u32 a0,u32 a1,u32 a2,u32 a3,
                                         u32 b0,u32 b1){
    asm volatile(
      "mma.sync.aligned.m16n8k16.row.col.f32.bf16.bf16.f32 "
      "{%0,%1,%2,%3}, {%4,%5,%6,%7}, {%8,%9}, {%0,%1,%2,%3};"
      : "+f"(c[0]), "+f"(c[1]), "+f"(c[2]), "+f"(c[3])
      : "r"(a0), "r"(a1), "r"(a2), "r"(a3), "r"(b0), "r"(b1));
}

// S-style mma: c[8][4] += A(q x d, split) * B(kn x d in [row][72] layout)^T
__device__ __forceinline__ void mma_block(float c[8][4],
                                          const u32 qh[4][4], const u32 ql[4][4],
                                          const __nv_bfloat16* __restrict__ KH,
                                          const __nv_bfloat16* __restrict__ KL,
                                          int grp, int cc){
#pragma unroll
    for (int nc = 0; nc < 8; nc++){
#pragma unroll
        for (int kc = 0; kc < 4; kc++){
            const __nv_bfloat16* ph = KH + (8*nc+grp)*72 + 16*kc + 2*cc;
            const __nv_bfloat16* pl = KL + (8*nc+grp)*72 + 16*kc + 2*cc;
            u32 bh0 = *(const u32*)ph;
            u32 bh1 = *(const u32*)(ph + 8);
            u32 bl0 = *(const u32*)pl;
            u32 bl1 = *(const u32*)(pl + 8);
            mma16816(c[nc], qh[kc][0], qh[kc][1], qh[kc][2], qh[kc][3], bh0, bh1);
            mma16816(c[nc], qh[kc][0], qh[kc][1], qh[kc][2], qh[kc][3], bl0, bl1);
            mma16816(c[nc], ql[kc][0], ql[kc][1], ql[kc][2], ql[kc][3], bh0, bh1);
        }
    }
}

// ======================= Kernel 1: qkv GEMM + split epilogue ===============
__global__ __launch_bounds__(256, 2)
void qkv_gemm_kernel(const float* __restrict__ A,
                     const float* __restrict__ Wv,
                     const float* __restrict__ bias)
{
    __shared__ float As[16][132];
    __shared__ float Bs[16][132];
    const int t  = threadIdx.x;
    const int tx = t & 15, ty = t >> 4;
    const int n0 = blockIdx.x * 128;
    const int m0 = blockIdx.y * 128;

    float acc[8][8];
#pragma unroll
    for (int i = 0; i < 8; i++)
#pragma unroll
        for (int j = 0; j < 8; j++) acc[i][j] = 0.f;

    for (int k0 = 0; k0 < 512; k0 += 16) {
        __syncthreads();
#pragma unroll
        for (int c = 0; c < 2; c++) {
            int i0 = t + c * 256;
            int m = i0 >> 2, kv = i0 & 3;
            float4 v = *(const float4*)(A + (size_t)(m0 + m) * 512 + k0 + kv * 4);
            As[kv * 4 + 0][m] = v.x; As[kv * 4 + 1][m] = v.y;
            As[kv * 4 + 2][m] = v.z; As[kv * 4 + 3][m] = v.w;
        }
#pragma unroll
        for (int c = 0; c < 2; c++) {
            int i0 = t + c * 256;
            int k = i0 >> 5, nv = i0 & 31;
            *(float4*)&Bs[k][nv * 4] =
                *(const float4*)(Wv + (size_t)(k0 + k) * 1536 + n0 + nv * 4);
        }
        __syncthreads();
#pragma unroll
        for (int kk = 0; kk < 16; kk++) {
            float a_[8], b_[8];
            *(float4*)&a_[0] = *(float4*)&As[kk][ty * 8];
            *(float4*)&a_[4] = *(float4*)&As[kk][ty * 8 + 4];
            *(float4*)&b_[0] = *(float4*)&Bs[kk][tx * 8];
            *(float4*)&b_[4] = *(float4*)&Bs[kk][tx * 8 + 4];
#pragma unroll
            for (int i = 0; i < 8; i++)
#pragma unroll
                for (int j = 0; j < 8; j++)
                    acc[i][j] += a_[i] * b_[j];
        }
    }

#pragma unroll
    for (int i = 0; i < 8; i++) {
        int m = m0 + ty * 8 + i;
        int b = m >> 10, s = m & 1023;
#pragma unroll
        for (int jj = 0; jj < 2; jj++) {
            int n = n0 + tx * 8 + jj * 4;
            int part = n >> 9;
            int r = n & 511;
            int hd = r >> 6, d = r & 63;
            float sc = (part == 0) ? 0.125f : 1.f;
            float vv[4];
#pragma unroll
            for (int e = 0; e < 4; e++) vv[e] = (acc[i][jj*4+e] + bias[n+e]) * sc;
            __nv_bfloat16 hb[4], lb[4];
#pragma unroll
            for (int e = 0; e < 4; e++) split_bf(vv[e], hb[e], lb[e]);
            uint2 hp; hp.x = pack2(hb[0], hb[1]); hp.y = pack2(hb[2], hb[3]);
            uint2 lp; lp.x = pack2(lb[0], lb[1]); lp.y = pack2(lb[2], lb[3]);
            size_t off = ((size_t)(b*8 + hd) * 1024 + s) * 64 + d;
            __nv_bfloat16* H = (part == 0) ? g_Qh : (part == 1) ? g_Kh : g_Vh;
            __nv_bfloat16* L = (part == 0) ? g_Ql : (part == 1) ? g_Kl : g_Vl;
            *(uint2*)(H + off) = hp;
            *(uint2*)(L + off) = lp;
        }
    }
}

// ======================= Kernel 1b: V transpose ============================
__global__ __launch_bounds__(256)
void vtrans_kernel()
{
    __shared__ __nv_bfloat16 th[64][72];
    __shared__ __nv_bfloat16 tl[64][72];
    const int t = threadIdx.x;
    const int s0 = blockIdx.x * 64;
    const int bh = blockIdx.y;

    for (int i = t; i < 2048; i += 256) {
        int sl = i >> 5, dp = i & 31;
        size_t src = ((size_t)bh * 1024 + s0 + sl) * 64 + 2*dp;
        *(u32*)&th[sl][2*dp] = *(const u32*)(g_Vh + src);
        *(u32*)&tl[sl][2*dp] = *(const u32*)(g_Vl + src);
    }
    __syncthreads();
    for (int i = t; i < 2048; i += 256) {
        int d = i >> 5, sp = i & 31;
        size_t dst = ((size_t)bh * 64 + d) * 1024 + s0 + 2*sp;
        *(u32*)(g_Vth + dst) = pack2(th[2*sp][d], th[2*sp+1][d]);
        *(u32*)(g_Vtl + dst) = pack2(tl[2*sp][d], tl[2*sp+1][d]);
    }
}

// ======================= Kernel 2: fused attention (tensor core) ===========
// 128 threads (4 warps), q-tile 64, two-pass flash + rel-pos via Qp/Ap.
#define OFF_QH 0
#define OFF_QL 9216
#define OFF_KH 18432
#define OFF_KL 27648
#define OFF_VH 36864
#define OFF_VL 46080
#define OFF_QP 55296
#define OFF_AP 122880
#define OFF_MSK 190464
#define ATTN_SMEM (190464 + 256)

__global__ __launch_bounds__(128)
void attn_kernel(const int* __restrict__ mask,
                 const float* __restrict__ posK,
                 const float* __restrict__ posV)
{
    extern __shared__ char sm[];
    __nv_bfloat16* QH = (__nv_bfloat16*)(sm + OFF_QH);
    __nv_bfloat16* QL = (__nv_bfloat16*)(sm + OFF_QL);
    __nv_bfloat16* KH = (__nv_bfloat16*)(sm + OFF_KH);
    __nv_bfloat16* KL = (__nv_bfloat16*)(sm + OFF_KL);
    __nv_bfloat16* VH = (__nv_bfloat16*)(sm + OFF_VH);
    __nv_bfloat16* VL = (__nv_bfloat16*)(sm + OFF_VL);
    float* QP  = (float*)(sm + OFF_QP);   // [64][264]
    float* AP  = (float*)(sm + OFF_AP);   // [64][264]
    float* MSK = (float*)(sm + OFF_MSK);  // [64]

    const int t = threadIdx.x;
    const int w = t >> 5, lane = t & 31, grp = lane >> 2, cc = lane & 3;
    const int q0 = blockIdx.x * 64;
    const int bh = blockIdx.y;
    const int bb = bh >> 3, hh = bh & 7;
    const int r_lo = w * 16 + grp;            // tile-local q row (c0/c1)
    const int qg0 = q0 + r_lo, qg1 = qg0 + 8;

    // ---- load Q tile, zero AP ----
    for (int i = t; i < 2048; i += 128) {
        int r = i >> 5, dp = i & 31;
        size_t src = ((size_t)bh * 1024 + q0 + r) * 64 + 2*dp;
        *(u32*)&QH[r*72 + 2*dp] = *(const u32*)(g_Qh + src);
        *(u32*)&QL[r*72 + 2*dp] = *(const u32*)(g_Ql + src);
    }
    for (int i = t; i < 64*264; i += 128) AP[i] = 0.f;
    __syncthreads();

    // ---- Q A-fragments (reused everywhere) ----
    u32 qa_h[4][4], qa_l[4][4];
#pragma unroll
    for (int kc = 0; kc < 4; kc++) {
        int col = 16*kc + 2*cc;
        qa_h[kc][0] = *(u32*)&QH[ r_lo    *72 + col];
        qa_h[kc][1] = *(u32*)&QH[(r_lo+8)*72 + col];
        qa_h[kc][2] = *(u32*)&QH[ r_lo    *72 + col + 8];
        qa_h[kc][3] = *(u32*)&QH[(r_lo+8)*72 + col + 8];
        qa_l[kc][0] = *(u32*)&QL[ r_lo    *72 + col];
        qa_l[kc][1] = *(u32*)&QL[(r_lo+8)*72 + col];
        qa_l[kc][2] = *(u32*)&QL[ r_lo    *72 + col + 8];
        qa_l[kc][3] = *(u32*)&QL[(r_lo+8)*72 + col + 8];
    }

    // ---- Qp[q][r] = Q . posK^T  (5 r-tiles of 64, posK zero-padded) ----
    for (int rt = 0; rt < 5; rt++) {
        int r0 = rt * 64;
        __syncthreads();
        for (int i = t; i < 2048; i += 128) {
            int r = i >> 5, dp = i & 31;
            int rg = r0 + r;
            float2 pv = (rg < 257) ? *(const float2*)(posK + rg*64 + 2*dp)
                                   : make_float2(0.f, 0.f);
            __nv_bfloat16 h0,l0,h1,l1;
            split_bf(pv.x, h0, l0); split_bf(pv.y, h1, l1);
            *(u32*)&KH[r*72 + 2*dp] = pack2(h0, h1);
            *(u32*)&KL[r*72 + 2*dp] = pack2(l0, l1);
        }
        __syncthreads();
        float c[8][4];
#pragma unroll
        for (int nc = 0; nc < 8; nc++)
#pragma unroll
            for (int e = 0; e < 4; e++) c[nc][e] = 0.f;
        mma_block(c, qa_h, qa_l, KH, KL, grp, cc);
#pragma unroll
        for (int nc = 0; nc < 8; nc++) {
            int r = r0 + 8*nc + 2*cc;
            if (r < 257) {
                QP[ r_lo    *264 + r] = c[nc][0];
                QP[(r_lo+8) *264 + r] = c[nc][2];
            }
            if (r + 1 < 257) {
                QP[ r_lo    *264 + r + 1] = c[nc][1];
                QP[(r_lo+8) *264 + r + 1] = c[nc][3];
            }
        }
    }

    // ---- pass 1: row stats (m, l) -> z = m + log l ----
    float m0 = -1e30f, m1 = -1e30f, l0 = 0.f, l1 = 0.f;
    for (int kt = 0; kt < 16; kt++) {
        int k0 = kt * 64;
        __syncthreads();
        for (int i = t; i < 2048; i += 128) {
            int k = i >> 5, dp = i & 31;
            size_t src = ((size_t)bh * 1024 + k0 + k) * 64 + 2*dp;
            *(u32*)&KH[k*72 + 2*dp] = *(const u32*)(g_Kh + src);
            *(u32*)&KL[k*72 + 2*dp] = *(const u32*)(g_Kl + src);
        }
        if (t < 64) MSK[t] = mask[bb*1024 + k0 + t] ? 0.f : -1e30f;
        __syncthreads();

        float c[8][4];
#pragma unroll
        for (int nc = 0; nc < 8; nc++)
#pragma unroll
            for (int e = 0; e < 4; e++) c[nc][e] = 0.f;
        mma_block(c, qa_h, qa_l, KH, KL, grp, cc);

        float tm0 = -1e30f, tm1 = -1e30f;
#pragma unroll
        for (int nc = 0; nc < 8; nc++) {
            int kg = k0 + 8*nc + 2*cc;
            float bias0 = MSK[8*nc + 2*cc], bias1 = MSK[8*nc + 2*cc + 1];
            int rA0 = min(max(kg     - qg0, -128), 128) + 128;
            int rA1 = min(max(kg + 1 - qg0, -128), 128) + 128;
            int rB0 = min(max(kg     - qg1, -128), 128) + 128;
            int rB1 = min(max(kg + 1 - qg1, -128), 128) + 128;
            c[nc][0] += QP[ r_lo   *264 + rA0] + bias0;
            c[nc][1] += QP[ r_lo   *264 + rA1] + bias1;
            c[nc][2] += QP[(r_lo+8)*264 + rB0] + bias0;
            c[nc][3] += QP[(r_lo+8)*264 + rB1] + bias1;
            tm0 = fmaxf(tm0, fmaxf(c[nc][0], c[nc][1]));
            tm1 = fmaxf(tm1, fmaxf(c[nc][2], c[nc][3]));
        }
        tm0 = fmaxf(tm0, __shfl_xor_sync(0xffffffffu, tm0, 1));
        tm0 = fmaxf(tm0, __shfl_xor_sync(0xffffffffu, tm0, 2));
        tm1 = fmaxf(tm1, __shfl_xor_sync(0xffffffffu, tm1, 1));
        tm1 = fmaxf(tm1, __shfl_xor_sync(0xffffffffu, tm1, 2));
        float mn0 = fmaxf(m0, tm0), mn1 = fmaxf(m1, tm1);
        float f0 = __expf(m0 - mn0), f1 = __expf(m1 - mn1);
        float s0 = 0.f, s1 = 0.f;
#pragma unroll
        for (int nc = 0; nc < 8; nc++) {
            s0 += __expf(c[nc][0] - mn0) + __expf(c[nc][1] - mn0);
            s1 += __expf(c[nc][2] - mn1) + __expf(c[nc][3] - mn1);
        }
        l0 = l0 * f0 + s0; m0 = mn0;
        l1 = l1 * f1 + s1; m1 = mn1;
    }
    l0 += __shfl_xor_sync(0xffffffffu, l0, 1);
    l0 += __shfl_xor_sync(0xffffffffu, l0, 2);
    l1 += __shfl_xor_sync(0xffffffffu, l1, 1);
    l1 += __shfl_xor_sync(0xffffffffu, l1, 2);
    const float z0 = m0 + __logf(l0);
    const float z1 = m1 + __logf(l1);

    // ---- pass 2: P = exp(S - z); O1 += P V; Ap scatter ----
    float o[8][4];
#pragma unroll
    for (int nc = 0; nc < 8; nc++)
#pragma unroll
        for (int e = 0; e < 4; e++) o[nc][e] = 0.f;
    float bin0a = 0.f, bin0b = 0.f, bin256a = 0.f, bin256b = 0.f;

    for (int kt = 0; kt < 16; kt++) {
        int k0 = kt * 64;
        __syncthreads();
        for (int i = t; i < 2048; i += 128) {
            int k = i >> 5, dp = i & 31;
            size_t srcK = ((size_t)bh * 1024 + k0 + k) * 64 + 2*dp;
            *(u32*)&KH[k*72 + 2*dp] = *(const u32*)(g_Kh + srcK);
            *(u32*)&KL[k*72 + 2*dp] = *(const u32*)(g_Kl + srcK);
            // V transposed tile: row d = k index here, col = key
            size_t srcV = ((size_t)bh * 64 + k) * 1024 + k0 + 2*dp;
            *(u32*)&VH[k*72 + 2*dp] = *(const u32*)(g_Vth + srcV);
            *(u32*)&VL[k*72 + 2*dp] = *(const u32*)(g_Vtl + srcV);
        }
        if (t < 64) MSK[t] = mask[bb*1024 + k0 + t] ? 0.f : -1e30f;
        __syncthreads();

        float c[8][4];
#pragma unroll
        for (int nc = 0; nc < 8; nc++)
#pragma unroll
            for (int e = 0; e < 4; e++) c[nc][e] = 0.f;
        mma_block(c, qa_h, qa_l, KH, KL, grp, cc);

        u32 ph[8][2], pl[8][2];
#pragma unroll
        for (int nc = 0; nc < 8; nc++) {
            int kg = k0 + 8*nc + 2*cc;
            float bias0 = MSK[8*nc + 2*cc], bias1 = MSK[8*nc + 2*cc + 1];
            int dA0 = kg     - qg0, dA1 = kg + 1 - qg0;
            int dB0 = kg     - qg1, dB1 = kg + 1 - qg1;
            float s00 = c[nc][0] + QP[ r_lo   *264 + min(max(dA0,-128),128)+128] + bias0;
            float s01 = c[nc][1] + QP[ r_lo   *264 + min(max(dA1,-128),128)+128] + bias1;
            float s10 = c[nc][2] + QP[(r_lo+8)*264 + min(max(dB0,-128),128)+128] + bias0;
            float s11 = c[nc][3] + QP[(r_lo+8)*264 + min(max(dB1,-128),128)+128] + bias1;
            float p00 = __expf(s00 - z0), p01 = __expf(s01 - z0);
            float p10 = __expf(s10 - z1), p11 = __expf(s11 - z1);
            // scatter to Ap (in-band slots are written at most once overall)
            if (dA0 <= -128) bin0a += p00; else if (dA0 >= 128) bin256a += p00;
            else AP[ r_lo   *264 + dA0 + 128] = p00;
            if (dA1 <= -128) bin0a += p01; else if (dA1 >= 128) bin256a += p01;
            else AP[ r_lo   *264 + dA1 + 128] = p01;
            if (dB0 <= -128) bin0b += p10; else if (dB0 >= 128) bin256b += p10;
            else AP[(r_lo+8)*264 + dB0 + 128] = p10;
            if (dB1 <= -128) bin0b += p11; else if (dB1 >= 128) bin256b += p11;
            else AP[(r_lo+8)*264 + dB1 + 128] = p11;
            // split P for the PV mma
            __nv_bfloat16 h00,l00,h01,l01,h10,l10,h11,l11;
            split_bf(p00, h00, l00); split_bf(p01, h01, l01);
            split_bf(p10, h10, l10); split_bf(p11, h11, l11);
            ph[nc][0] = pack2(h00, h01); pl[nc][0] = pack2(l00, l01);
            ph[nc][1] = pack2(h10, h11); pl[nc][1] = pack2(l10, l11);
        }

        // O1 += P @ V   (A = P from frags, B = V^T tiles)
#pragma unroll
        for (int nd = 0; nd < 8; nd++) {
#pragma unroll
            for (int kc = 0; kc < 4; kc++) {
                const __nv_bfloat16* pvh = VH + (8*nd+grp)*72 + 16*kc + 2*cc;
                const __nv_bfloat16* pvl = VL + (8*nd+grp)*72 + 16*kc + 2*cc;
                u32 bh0 = *(const u32*)pvh;
                u32 bh1 = *(const u32*)(pvh + 8);
                u32 bl0 = *(const u32*)pvl;
                u32 bl1 = *(const u32*)(pvl + 8);
                u32 a0 = ph[2*kc][0], a1 = ph[2*kc][1];
                u32 a2 = ph[2*kc+1][0], a3 = ph[2*kc+1][1];
                mma16816(o[nd], a0, a1, a2, a3, bh0, bh1);
                mma16816(o[nd], a0, a1, a2, a3, bl0, bl1);
                u32 la0 = pl[2*kc][0], la1 = pl[2*kc][1];
                u32 la2 = pl[2*kc+1][0], la3 = pl[2*kc+1][1];
                mma16816(o[nd], la0, la1, la2, la3, bh0, bh1);
            }
        }
    }

    // ---- clip bins into Ap ----
    bin0a   += __shfl_xor_sync(0xffffffffu, bin0a, 1);
    bin0a   += __shfl_xor_sync(0xffffffffu, bin0a, 2);
    bin0b   += __shfl_xor_sync(0xffffffffu, bin0b, 1);
    bin0b   += __shfl_xor_sync(0xffffffffu, bin0b, 2);
    bin256a += __shfl_xor_sync(0xffffffffu, bin256a, 1);
    bin256a += __shfl_xor_sync(0xffffffffu, bin256a, 2);
    bin256b += __shfl_xor_sync(0xffffffffu, bin256b, 1);
    bin256b += __shfl_xor_sync(0xffffffffu, bin256b, 2);
    if (cc == 0) {
        AP[ r_lo   *264 + 0]   = bin0a;
        AP[ r_lo   *264 + 256] = bin256a;
        AP[(r_lo+8)*264 + 0]   = bin0b;
        AP[(r_lo+8)*264 + 256] = bin256b;
    }
    __syncthreads();

    // ---- O2 = Ap @ posV (5 r-tiles, posV^T staged zero-padded) ----
    for (int rt = 0; rt < 5; rt++) {
        int r0 = rt * 64;
        for (int i = t; i < 4096; i += 128) {
            int r = i >> 6, d = i & 63;
            int rg = r0 + r;
            float v = (rg < 257) ? posV[rg*64 + d] : 0.f;
            __nv_bfloat16 hb, lb;
            split_bf(v, hb, lb);
            VH[d*72 + r] = hb;
            VL[d*72 + r] = lb;
        }
        __syncthreads();
#pragma unroll
        for (int kc = 0; kc < 4; kc++) {
            int rA = r0 + 16*kc + 2*cc;
            float v00 = (rA     < 257) ? AP[ r_lo   *264 + rA]     : 0.f;
            float v01 = (rA + 1 < 257) ? AP[ r_lo   *264 + rA + 1] : 0.f;
            float v10 = (rA     < 257) ? AP[(r_lo+8)*264 + rA]     : 0.f;
            float v11 = (rA + 1 < 257) ? AP[(r_lo+8)*264 + rA + 1] : 0.f;
            float v20 = (rA + 8 < 257) ? AP[ r_lo   *264 + rA + 8] : 0.f;
            float v21 = (rA + 9 < 257) ? AP[ r_lo   *264 + rA + 9] : 0.f;
            float v30 = (rA + 8 < 257) ? AP[(r_lo+8)*264 + rA + 8] : 0.f;
            float v31 = (rA + 9 < 257) ? AP[(r_lo+8)*264 + rA + 9] : 0.f;
            __nv_bfloat16 h[8], l[8];
            split_bf(v00, h[0], l[0]); split_bf(v01, h[1], l[1]);
            split_bf(v10, h[2], l[2]); split_bf(v11, h[3], l[3]);
            split_bf(v20, h[4], l[4]); split_bf(v21, h[5], l[5]);
            split_bf(v30, h[6], l[6]); split_bf(v31, h[7], l[7]);
            u32 ah0 = pack2(h[0], h[1]), ah1 = pack2(h[2], h[3]);
            u32 ah2 = pack2(h[4], h[5]), ah3 = pack2(h[6], h[7]);
            u32 al0 = pack2(l[0], l[1]), al1 = pack2(l[2], l[3]);
            u32 al2 = pack2(l[4], l[5]), al3 = pack2(l[6], l[7]);
#pragma unroll
            for (int nd = 0; nd < 8; nd++) {
                const __nv_bfloat16* pvh = VH + (8*nd+grp)*72 + 16*kc + 2*cc;
                const __nv_bfloat16* pvl = VL + (8*nd+grp)*72 + 16*kc + 2*cc;
                u32 bh0 = *(const u32*)pvh;
                u32 bh1 = *(const u32*)(pvh + 8);
                u32 bl0 = *(const u32*)pvl;
                u32 bl1 = *(const u32*)(pvl + 8);
                mma16816(o[nd], ah0, ah1, ah2, ah3, bh0, bh1);
                mma16816(o[nd], ah0, ah1, ah2, ah3, bl0, bl1);
                mma16816(o[nd], al0, al1, al2, al3, bh0, bh1);
            }
        }
        __syncthreads();
    }

    // ---- write O ----
#pragma unroll
    for (int nd = 0; nd < 8; nd++) {
        int d = hh*64 + 8*nd + 2*cc;
        float2 s0 = make_float2(o[nd][0], o[nd][1]);
        float2 s1 = make_float2(o[nd][2], o[nd][3]);
        *(float2*)&g_O[((size_t)bb*1024 + q0 + r_lo    ) * 512 + d] = s0;
        *(float2*)&g_O[((size_t)bb*1024 + q0 + r_lo + 8) * 512 + d] = s1;
    }
}

// ======================= Kernel 3: output GEMM =============================
__global__ __launch_bounds__(256, 2)
void out_gemm_kernel(const float* __restrict__ Wv,
                     const float* __restrict__ bias,
                     float* __restrict__ C)
{
    __shared__ float As[16][132];
    __shared__ float Bs[16][132];
    const int t  = threadIdx.x;
    const int tx = t & 15, ty = t >> 4;
    const int n0 = blockIdx.x * 128;
    const int m0 = blockIdx.y * 128;

    float acc[8][8];
#pragma unroll
    for (int i = 0; i < 8; i++)
#pragma unroll
        for (int j = 0; j < 8; j++) acc[i][j] = 0.f;

    for (int k0 = 0; k0 < 512; k0 += 16) {
        __syncthreads();
#pragma unroll
        for (int c = 0; c < 2; c++) {
            int i0 = t + c * 256;
            int m = i0 >> 2, kv = i0 & 3;
            float4 v = *(const float4*)(g_O + (size_t)(m0 + m) * 512 + k0 + kv * 4);
            As[kv * 4 + 0][m] = v.x; As[kv * 4 + 1][m] = v.y;
            As[kv * 4 + 2][m] = v.z; As[kv * 4 + 3][m] = v.w;
        }
#pragma unroll
        for (int c = 0; c < 2; c++) {
            int i0 = t + c * 256;
            int k = i0 >> 5, nv = i0 & 31;
            *(float4*)&Bs[k][nv * 4] =
                *(const float4*)(Wv + (size_t)(k0 + k) * 512 + n0 + nv * 4);
        }
        __syncthreads();
#pragma unroll
        for (int kk = 0; kk < 16; kk++) {
            float a_[8], b_[8];
            *(float4*)&a_[0] = *(float4*)&As[kk][ty * 8];
            *(float4*)&a_[4] = *(float4*)&As[kk][ty * 8 + 4];
            *(float4*)&b_[0] = *(float4*)&Bs[kk][tx * 8];
            *(float4*)&b_[4] = *(float4*)&Bs[kk][tx * 8 + 4];
#pragma unroll
            for (int i = 0; i < 8; i++)
#pragma unroll
                for (int j = 0; j < 8; j++)
                    acc[i][j] += a_[i] * b_[j];
        }
    }

#pragma unroll
    for (int i = 0; i < 8; i++) {
        int m = m0 + ty * 8 + i;
#pragma unroll
        for (int jj = 0; jj < 2; jj++) {
            int n = n0 + tx * 8 + jj * 4;
            float4 v;
            v.x = acc[i][jj * 4 + 0] + bias[n + 0];
            v.y = acc[i][jj * 4 + 1] + bias[n + 1];
            v.z = acc[i][jj * 4 + 2] + bias[n + 2];
            v.w = acc[i][jj * 4 + 3] + bias[n + 3];
            *(float4*)(C + (size_t)m * 512 + n) = v;
        }
    }
}

// ============================== launcher ===================================
extern "C" void kernel_launch(void* const* d_in, const int* in_sizes, int n_in,
                              void* d_out, int out_size)
{
    const float* x     = (const float*)d_in[0];
    const int*   mask  = (const int*)  d_in[1];
    const float* W_in  = (const float*)d_in[2];
    const float* b_in  = (const float*)d_in[3];
    const float* W_out = (const float*)d_in[4];
    const float* b_out = (const float*)d_in[5];
    const float* posK  = (const float*)d_in[6];
    const float* posV  = (const float*)d_in[7];
    float* out = (float*)d_out;
    (void)in_sizes; (void)n_in; (void)out_size;

    cudaFuncSetAttribute(attn_kernel,
                         cudaFuncAttributeMaxDynamicSharedMemorySize,
                         ATTN_SMEM);

    qkv_gemm_kernel<<<dim3(12, 64), 256>>>(x, W_in, b_in);
    vtrans_kernel<<<dim3(16, 64), 256>>>();
    attn_kernel<<<dim3(16, 64), 128, ATTN_SMEM>>>(mask, posK, posV);
    out_gemm_kernel<<<dim3(4, 64), 256>>>(W_out, b_out, out);
}

// round 4
// speedup vs baseline: 1.3847x; 1.3281x over previous
#include <cuda_runtime.h>
#include <cuda_bf16.h>
#include <math.h>

typedef unsigned int u32;

// ---------------------------------------------------------------------------
// Problem: B=8, S=1024, D=512, H=8, dh=64, MAX_POS=128
// inputs: 0:x f32[8,1024,512], 1:mask i32[8,1024], 2:W_in[512,1536],
//         3:b_in[1536], 4:W_out[512,512], 5:b_out[512],
//         6:pos_K[257,64], 7:pos_V[257,64];  output f32[8,1024,512]
// ---------------------------------------------------------------------------

// split-bf16 Q/K/V, layout [bh][s][d]; Q pre-scaled by 1/8
static __device__ __nv_bfloat16 g_Qh[8*8*1024*64];
static __device__ __nv_bfloat16 g_Ql[8*8*1024*64];
static __device__ __nv_bfloat16 g_Kh[8*8*1024*64];
static __device__ __nv_bfloat16 g_Kl[8*8*1024*64];
static __device__ __nv_bfloat16 g_Vh[8*8*1024*64];
static __device__ __nv_bfloat16 g_Vl[8*8*1024*64];
// V transposed: [bh][d][s]
static __device__ __nv_bfloat16 g_Vth[8*8*64*1024];
static __device__ __nv_bfloat16 g_Vtl[8*8*64*1024];
static __device__ float g_O[8192*512];            // [b,s,h*64+d]

// ---------------------------- helpers --------------------------------------
__device__ __forceinline__ u32 pack2(__nv_bfloat16 x, __nv_bfloat16 y){
    __nv_bfloat162 t; t.x = x; t.y = y;
    return *reinterpret_cast<u32*>(&t);
}
__device__ __forceinline__ void split_bf(float v, __nv_bfloat16& h, __nv_bfloat16& l){
    h = __float2bfloat16(v);
    l = __float2bfloat16(v - __bfloat162float(h));
}
__device__ __forceinline__ void mma16816(float c[4], u32 a0,u32 a1,u32 a2,u32 a3,
                                         u32 b0,u32 b1){
    asm volatile(
      "mma.sync.aligned.m16n8k16.row.col.f32.bf16.bf16.f32 "
      "{%0,%1,%2,%3}, {%4,%5,%6,%7}, {%8,%9}, {%0,%1,%2,%3};"
      : "+f"(c[0]), "+f"(c[1]), "+f"(c[2]), "+f"(c[3])
      : "r"(a0), "r"(a1), "r"(a2), "r"(a3), "r"(b0), "r"(b1));
}

// ======================= Kernel 1: qkv GEMM + split epilogue ===============
__global__ __launch_bounds__(256, 2)
void qkv_gemm_kernel(const float* __restrict__ A,
                     const float* __restrict__ Wv,
                     const float* __restrict__ bias)
{
    __shared__ float As[16][132];
    __shared__ float Bs[16][132];
    const int t  = threadIdx.x;
    const int tx = t & 15, ty = t >> 4;
    const int n0 = blockIdx.x * 128;
    const int m0 = blockIdx.y * 128;

    float acc[8][8];
#pragma unroll
    for (int i = 0; i < 8; i++)
#pragma unroll
        for (int j = 0; j < 8; j++) acc[i][j] = 0.f;

    for (int k0 = 0; k0 < 512; k0 += 16) {
        __syncthreads();
#pragma unroll
        for (int c = 0; c < 2; c++) {
            int i0 = t + c * 256;
            int m = i0 >> 2, kv = i0 & 3;
            float4 v = *(const float4*)(A + (size_t)(m0 + m) * 512 + k0 + kv * 4);
            As[kv * 4 + 0][m] = v.x; As[kv * 4 + 1][m] = v.y;
            As[kv * 4 + 2][m] = v.z; As[kv * 4 + 3][m] = v.w;
        }
#pragma unroll
        for (int c = 0; c < 2; c++) {
            int i0 = t + c * 256;
            int k = i0 >> 5, nv = i0 & 31;
            *(float4*)&Bs[k][nv * 4] =
                *(const float4*)(Wv + (size_t)(k0 + k) * 1536 + n0 + nv * 4);
        }
        __syncthreads();
#pragma unroll
        for (int kk = 0; kk < 16; kk++) {
            float a_[8], b_[8];
            *(float4*)&a_[0] = *(float4*)&As[kk][ty * 8];
            *(float4*)&a_[4] = *(float4*)&As[kk][ty * 8 + 4];
            *(float4*)&b_[0] = *(float4*)&Bs[kk][tx * 8];
            *(float4*)&b_[4] = *(float4*)&Bs[kk][tx * 8 + 4];
#pragma unroll
            for (int i = 0; i < 8; i++)
#pragma unroll
                for (int j = 0; j < 8; j++)
                    acc[i][j] += a_[i] * b_[j];
        }
    }

#pragma unroll
    for (int i = 0; i < 8; i++) {
        int m = m0 + ty * 8 + i;
        int b = m >> 10, s = m & 1023;
#pragma unroll
        for (int jj = 0; jj < 2; jj++) {
            int n = n0 + tx * 8 + jj * 4;
            int part = n >> 9;
            int r = n & 511;
            int hd = r >> 6, d = r & 63;
            float sc = (part == 0) ? 0.125f : 1.f;
            float vv[4];
#pragma unroll
            for (int e = 0; e < 4; e++) vv[e] = (acc[i][jj*4+e] + bias[n+e]) * sc;
            __nv_bfloat16 hb[4], lb[4];
#pragma unroll
            for (int e = 0; e < 4; e++) split_bf(vv[e], hb[e], lb[e]);
            uint2 hp; hp.x = pack2(hb[0], hb[1]); hp.y = pack2(hb[2], hb[3]);
            uint2 lp; lp.x = pack2(lb[0], lb[1]); lp.y = pack2(lb[2], lb[3]);
            size_t off = ((size_t)(b*8 + hd) * 1024 + s) * 64 + d;
            __nv_bfloat16* H = (part == 0) ? g_Qh : (part == 1) ? g_Kh : g_Vh;
            __nv_bfloat16* L = (part == 0) ? g_Ql : (part == 1) ? g_Kl : g_Vl;
            *(uint2*)(H + off) = hp;
            *(uint2*)(L + off) = lp;
        }
    }
}

// ======================= Kernel 1b: V transpose ============================
__global__ __launch_bounds__(256)
void vtrans_kernel()
{
    __shared__ __nv_bfloat16 th[64][72];
    __shared__ __nv_bfloat16 tl[64][72];
    const int t = threadIdx.x;
    const int s0 = blockIdx.x * 64;
    const int bh = blockIdx.y;

    for (int i = t; i < 2048; i += 256) {
        int sl = i >> 5, dp = i & 31;
        size_t src = ((size_t)bh * 1024 + s0 + sl) * 64 + 2*dp;
        *(u32*)&th[sl][2*dp] = *(const u32*)(g_Vh + src);
        *(u32*)&tl[sl][2*dp] = *(const u32*)(g_Vl + src);
    }
    __syncthreads();
    for (int i = t; i < 2048; i += 256) {
        int d = i >> 5, sp = i & 31;
        size_t dst = ((size_t)bh * 64 + d) * 1024 + s0 + 2*sp;
        *(u32*)(g_Vth + dst) = pack2(th[2*sp][d], th[2*sp+1][d]);
        *(u32*)(g_Vtl + dst) = pack2(tl[2*sp][d], tl[2*sp+1][d]);
    }
}

// ======================= Kernel 2: fused attention (tensor core) ===========
// 256 threads (8 warps), q-tile 64. Warp (wq, wn): wq = row-group (16 q rows),
// wn = column half (32 of 64 k columns). Two-pass: pass1 = hi-only max,
// pass2 = exact P, PV, Ap scatter, lsum; final divide by lsum.
#define OFF_QH 0
#define OFF_QL 9216
#define OFF_KH 18432
#define OFF_KL 27648
#define OFF_VH 36864
#define OFF_VL 46080
#define OFF_QP 55296
#define OFF_AP 122880
#define OFF_MSK 190464
#define OFF_RED 190720
#define ATTN_SMEM (190720 + 512)

__global__ __launch_bounds__(256)
void attn_kernel(const int* __restrict__ mask,
                 const float* __restrict__ posK,
                 const float* __restrict__ posV)
{
    extern __shared__ char sm[];
    __nv_bfloat16* QH = (__nv_bfloat16*)(sm + OFF_QH);
    __nv_bfloat16* QL = (__nv_bfloat16*)(sm + OFF_QL);
    __nv_bfloat16* KH = (__nv_bfloat16*)(sm + OFF_KH);
    __nv_bfloat16* KL = (__nv_bfloat16*)(sm + OFF_KL);
    __nv_bfloat16* VH = (__nv_bfloat16*)(sm + OFF_VH);
    __nv_bfloat16* VL = (__nv_bfloat16*)(sm + OFF_VL);
    float* QP  = (float*)(sm + OFF_QP);   // [64][264]
    float* AP  = (float*)(sm + OFF_AP);   // [64][264]
    float* MSK = (float*)(sm + OFF_MSK);  // [64]
    float* RED = (float*)(sm + OFF_RED);  // [2][64]

    const int t = threadIdx.x;
    const int w = t >> 5, lane = t & 31, grp = lane >> 2, cc = lane & 3;
    const int wq = w & 3, wn = w >> 2;
    const int q0 = blockIdx.x * 64;
    const int bh = blockIdx.y;
    const int bb = bh >> 3, hh = bh & 7;
    const int r_lo = wq * 16 + grp;
    const int qg0 = q0 + r_lo, qg1 = qg0 + 8;

    // ---- load Q tile, zero AP ----
    for (int i = t; i < 2048; i += 256) {
        int r = i >> 5, dp = i & 31;
        size_t src = ((size_t)bh * 1024 + q0 + r) * 64 + 2*dp;
        *(u32*)&QH[r*72 + 2*dp] = *(const u32*)(g_Qh + src);
        *(u32*)&QL[r*72 + 2*dp] = *(const u32*)(g_Ql + src);
    }
    for (int i = t; i < 64*264; i += 256) AP[i] = 0.f;
    __syncthreads();

    // ---- Q A-fragments ----
    u32 qa_h[4][4], qa_l[4][4];
#pragma unroll
    for (int kc = 0; kc < 4; kc++) {
        int col = 16*kc + 2*cc;
        qa_h[kc][0] = *(u32*)&QH[ r_lo    *72 + col];
        qa_h[kc][1] = *(u32*)&QH[(r_lo+8)*72 + col];
        qa_h[kc][2] = *(u32*)&QH[ r_lo    *72 + col + 8];
        qa_h[kc][3] = *(u32*)&QH[(r_lo+8)*72 + col + 8];
        qa_l[kc][0] = *(u32*)&QL[ r_lo    *72 + col];
        qa_l[kc][1] = *(u32*)&QL[(r_lo+8)*72 + col];
        qa_l[kc][2] = *(u32*)&QL[ r_lo    *72 + col + 8];
        qa_l[kc][3] = *(u32*)&QL[(r_lo+8)*72 + col + 8];
    }

    // ---- Qp[q][r] = Q . posK^T  (5 r-tiles of 64, warp handles its half) ----
    for (int rt = 0; rt < 5; rt++) {
        int r0 = rt * 64;
        __syncthreads();
        for (int i = t; i < 2048; i += 256) {
            int r = i >> 5, dp = i & 31;
            int rg = r0 + r;
            float2 pv = (rg < 257) ? *(const float2*)(posK + rg*64 + 2*dp)
                                   : make_float2(0.f, 0.f);
            __nv_bfloat16 h0,l0,h1,l1;
            split_bf(pv.x, h0, l0); split_bf(pv.y, h1, l1);
            *(u32*)&KH[r*72 + 2*dp] = pack2(h0, h1);
            *(u32*)&KL[r*72 + 2*dp] = pack2(l0, l1);
        }
        __syncthreads();
        float c[4][4];
#pragma unroll
        for (int n4 = 0; n4 < 4; n4++)
#pragma unroll
            for (int e = 0; e < 4; e++) c[n4][e] = 0.f;
#pragma unroll
        for (int n4 = 0; n4 < 4; n4++) {
            int nc = 4*wn + n4;
#pragma unroll
            for (int kc = 0; kc < 4; kc++) {
                const __nv_bfloat16* ph = KH + (8*nc+grp)*72 + 16*kc + 2*cc;
                const __nv_bfloat16* pl = KL + (8*nc+grp)*72 + 16*kc + 2*cc;
                u32 bh0 = *(const u32*)ph, bh1 = *(const u32*)(ph + 8);
                u32 bl0 = *(const u32*)pl, bl1 = *(const u32*)(pl + 8);
                mma16816(c[n4], qa_h[kc][0],qa_h[kc][1],qa_h[kc][2],qa_h[kc][3], bh0,bh1);
                mma16816(c[n4], qa_h[kc][0],qa_h[kc][1],qa_h[kc][2],qa_h[kc][3], bl0,bl1);
                mma16816(c[n4], qa_l[kc][0],qa_l[kc][1],qa_l[kc][2],qa_l[kc][3], bh0,bh1);
            }
        }
#pragma unroll
        for (int n4 = 0; n4 < 4; n4++) {
            int nc = 4*wn + n4;
            int r = r0 + 8*nc + 2*cc;
            if (r < 257) {
                QP[ r_lo    *264 + r] = c[n4][0];
                QP[(r_lo+8) *264 + r] = c[n4][2];
            }
            if (r + 1 < 257) {
                QP[ r_lo    *264 + r + 1] = c[n4][1];
                QP[(r_lo+8) *264 + r + 1] = c[n4][3];
            }
        }
    }

    // ---- pass 1: row max only (hi-only mma) ----
    float mA = -1e30f, mB = -1e30f;
    for (int kt = 0; kt < 16; kt++) {
        int k0 = kt * 64;
        __syncthreads();
        for (int i = t; i < 2048; i += 256) {
            int k = i >> 5, dp = i & 31;
            size_t src = ((size_t)bh * 1024 + k0 + k) * 64 + 2*dp;
            *(u32*)&KH[k*72 + 2*dp] = *(const u32*)(g_Kh + src);
            *(u32*)&KL[k*72 + 2*dp] = *(const u32*)(g_Kl + src);
        }
        if (t < 64) MSK[t] = mask[bb*1024 + k0 + t] ? 0.f : -1e30f;
        __syncthreads();

        float c[4][4];
#pragma unroll
        for (int n4 = 0; n4 < 4; n4++)
#pragma unroll
            for (int e = 0; e < 4; e++) c[n4][e] = 0.f;
#pragma unroll
        for (int n4 = 0; n4 < 4; n4++) {
            int nc = 4*wn + n4;
#pragma unroll
            for (int kc = 0; kc < 4; kc++) {
                const __nv_bfloat16* ph = KH + (8*nc+grp)*72 + 16*kc + 2*cc;
                u32 bh0 = *(const u32*)ph, bh1 = *(const u32*)(ph + 8);
                mma16816(c[n4], qa_h[kc][0],qa_h[kc][1],qa_h[kc][2],qa_h[kc][3], bh0,bh1);
            }
        }
#pragma unroll
        for (int n4 = 0; n4 < 4; n4++) {
            int nc = 4*wn + n4;
            int kg = k0 + 8*nc + 2*cc;
            float bias0 = MSK[8*nc + 2*cc], bias1 = MSK[8*nc + 2*cc + 1];
            int rA0 = min(max(kg     - qg0, -128), 128) + 128;
            int rA1 = min(max(kg + 1 - qg0, -128), 128) + 128;
            int rB0 = min(max(kg     - qg1, -128), 128) + 128;
            int rB1 = min(max(kg + 1 - qg1, -128), 128) + 128;
            float s00 = c[n4][0] + QP[ r_lo   *264 + rA0] + bias0;
            float s01 = c[n4][1] + QP[ r_lo   *264 + rA1] + bias1;
            float s10 = c[n4][2] + QP[(r_lo+8)*264 + rB0] + bias0;
            float s11 = c[n4][3] + QP[(r_lo+8)*264 + rB1] + bias1;
            mA = fmaxf(mA, fmaxf(s00, s01));
            mB = fmaxf(mB, fmaxf(s10, s11));
        }
    }
    mA = fmaxf(mA, __shfl_xor_sync(0xffffffffu, mA, 1));
    mA = fmaxf(mA, __shfl_xor_sync(0xffffffffu, mA, 2));
    mB = fmaxf(mB, __shfl_xor_sync(0xffffffffu, mB, 1));
    mB = fmaxf(mB, __shfl_xor_sync(0xffffffffu, mB, 2));
    if (cc == 0) {
        RED[wn*64 + r_lo]     = mA;
        RED[wn*64 + r_lo + 8] = mB;
    }
    __syncthreads();
    const float z0 = fmaxf(RED[r_lo],     RED[64 + r_lo]);
    const float z1 = fmaxf(RED[r_lo + 8], RED[64 + r_lo + 8]);

    // ---- pass 2: P = exp(S - z); O += P V; Ap scatter; lsum ----
    float o[8][4];
#pragma unroll
    for (int nd = 0; nd < 8; nd++)
#pragma unroll
        for (int e = 0; e < 4; e++) o[nd][e] = 0.f;
    float bin0a = 0.f, bin0b = 0.f, bin256a = 0.f, bin256b = 0.f;
    float ls0 = 0.f, ls1 = 0.f;

    for (int kt = 0; kt < 16; kt++) {
        int k0 = kt * 64;
        __syncthreads();
        for (int i = t; i < 2048; i += 256) {
            int k = i >> 5, dp = i & 31;
            size_t srcK = ((size_t)bh * 1024 + k0 + k) * 64 + 2*dp;
            *(u32*)&KH[k*72 + 2*dp] = *(const u32*)(g_Kh + srcK);
            *(u32*)&KL[k*72 + 2*dp] = *(const u32*)(g_Kl + srcK);
            size_t srcV = ((size_t)bh * 64 + k) * 1024 + k0 + 2*dp;
            *(u32*)&VH[k*72 + 2*dp] = *(const u32*)(g_Vth + srcV);
            *(u32*)&VL[k*72 + 2*dp] = *(const u32*)(g_Vtl + srcV);
        }
        if (t < 64) MSK[t] = mask[bb*1024 + k0 + t] ? 0.f : -1e30f;
        __syncthreads();

        float c[4][4];
#pragma unroll
        for (int n4 = 0; n4 < 4; n4++)
#pragma unroll
            for (int e = 0; e < 4; e++) c[n4][e] = 0.f;
#pragma unroll
        for (int n4 = 0; n4 < 4; n4++) {
            int nc = 4*wn + n4;
#pragma unroll
            for (int kc = 0; kc < 4; kc++) {
                const __nv_bfloat16* ph = KH + (8*nc+grp)*72 + 16*kc + 2*cc;
                const __nv_bfloat16* pl = KL + (8*nc+grp)*72 + 16*kc + 2*cc;
                u32 bh0 = *(const u32*)ph, bh1 = *(const u32*)(ph + 8);
                u32 bl0 = *(const u32*)pl, bl1 = *(const u32*)(pl + 8);
                mma16816(c[n4], qa_h[kc][0],qa_h[kc][1],qa_h[kc][2],qa_h[kc][3], bh0,bh1);
                mma16816(c[n4], qa_h[kc][0],qa_h[kc][1],qa_h[kc][2],qa_h[kc][3], bl0,bl1);
                mma16816(c[n4], qa_l[kc][0],qa_l[kc][1],qa_l[kc][2],qa_l[kc][3], bh0,bh1);
            }
        }

        u32 ph[4][2], pl[4][2];
#pragma unroll
        for (int n4 = 0; n4 < 4; n4++) {
            int nc = 4*wn + n4;
            int kg = k0 + 8*nc + 2*cc;
            float bias0 = MSK[8*nc + 2*cc], bias1 = MSK[8*nc + 2*cc + 1];
            int dA0 = kg     - qg0, dA1 = kg + 1 - qg0;
            int dB0 = kg     - qg1, dB1 = kg + 1 - qg1;
            float s00 = c[n4][0] + QP[ r_lo   *264 + min(max(dA0,-128),128)+128] + bias0;
            float s01 = c[n4][1] + QP[ r_lo   *264 + min(max(dA1,-128),128)+128] + bias1;
            float s10 = c[n4][2] + QP[(r_lo+8)*264 + min(max(dB0,-128),128)+128] + bias0;
            float s11 = c[n4][3] + QP[(r_lo+8)*264 + min(max(dB1,-128),128)+128] + bias1;
            float p00 = __expf(s00 - z0), p01 = __expf(s01 - z0);
            float p10 = __expf(s10 - z1), p11 = __expf(s11 - z1);
            ls0 += p00 + p01;
            ls1 += p10 + p11;
            if (dA0 <= -128) bin0a += p00; else if (dA0 >= 128) bin256a += p00;
            else AP[ r_lo   *264 + dA0 + 128] = p00;
            if (dA1 <= -128) bin0a += p01; else if (dA1 >= 128) bin256a += p01;
            else AP[ r_lo   *264 + dA1 + 128] = p01;
            if (dB0 <= -128) bin0b += p10; else if (dB0 >= 128) bin256b += p10;
            else AP[(r_lo+8)*264 + dB0 + 128] = p10;
            if (dB1 <= -128) bin0b += p11; else if (dB1 >= 128) bin256b += p11;
            else AP[(r_lo+8)*264 + dB1 + 128] = p11;
            __nv_bfloat16 h00,l00,h01,l01,h10,l10,h11,l11;
            split_bf(p00, h00, l00); split_bf(p01, h01, l01);
            split_bf(p10, h10, l10); split_bf(p11, h11, l11);
            ph[n4][0] = pack2(h00, h01); pl[n4][0] = pack2(l00, l01);
            ph[n4][1] = pack2(h10, h11); pl[n4][1] = pack2(l10, l11);
        }

        // O += P @ V  (warp's 32-column k half = kc slices {2wn, 2wn+1})
#pragma unroll
        for (int nd = 0; nd < 8; nd++) {
#pragma unroll
            for (int c2 = 0; c2 < 2; c2++) {
                int kc = 2*wn + c2;
                const __nv_bfloat16* pvh = VH + (8*nd+grp)*72 + 16*kc + 2*cc;
                const __nv_bfloat16* pvl = VL + (8*nd+grp)*72 + 16*kc + 2*cc;
                u32 bh0 = *(const u32*)pvh, bh1 = *(const u32*)(pvh + 8);
                u32 bl0 = *(const u32*)pvl, bl1 = *(const u32*)(pvl + 8);
                u32 a0 = ph[2*c2][0],   a1 = ph[2*c2][1];
                u32 a2 = ph[2*c2+1][0], a3 = ph[2*c2+1][1];
                mma16816(o[nd], a0, a1, a2, a3, bh0, bh1);
                mma16816(o[nd], a0, a1, a2, a3, bl0, bl1);
                u32 la0 = pl[2*c2][0],   la1 = pl[2*c2][1];
                u32 la2 = pl[2*c2+1][0], la3 = pl[2*c2+1][1];
                mma16816(o[nd], la0, la1, la2, la3, bh0, bh1);
            }
        }
    }

    // ---- clip bins + lsum ----
    bin0a   += __shfl_xor_sync(0xffffffffu, bin0a, 1);
    bin0a   += __shfl_xor_sync(0xffffffffu, bin0a, 2);
    bin0b   += __shfl_xor_sync(0xffffffffu, bin0b, 1);
    bin0b   += __shfl_xor_sync(0xffffffffu, bin0b, 2);
    bin256a += __shfl_xor_sync(0xffffffffu, bin256a, 1);
    bin256a += __shfl_xor_sync(0xffffffffu, bin256a, 2);
    bin256b += __shfl_xor_sync(0xffffffffu, bin256b, 1);
    bin256b += __shfl_xor_sync(0xffffffffu, bin256b, 2);
    ls0 += __shfl_xor_sync(0xffffffffu, ls0, 1);
    ls0 += __shfl_xor_sync(0xffffffffu, ls0, 2);
    ls1 += __shfl_xor_sync(0xffffffffu, ls1, 1);
    ls1 += __shfl_xor_sync(0xffffffffu, ls1, 2);
    if (cc == 0) {
        atomicAdd(&AP[ r_lo   *264 + 0],   bin0a);
        atomicAdd(&AP[ r_lo   *264 + 256], bin256a);
        atomicAdd(&AP[(r_lo+8)*264 + 0],   bin0b);
        atomicAdd(&AP[(r_lo+8)*264 + 256], bin256b);
        RED[wn*64 + r_lo]     = ls0;
        RED[wn*64 + r_lo + 8] = ls1;
    }
    __syncthreads();
    const float inv0 = 1.f / (RED[r_lo]     + RED[64 + r_lo]);
    const float inv1 = 1.f / (RED[r_lo + 8] + RED[64 + r_lo + 8]);

    // ---- O2 = Ap @ posV (5 r-tiles; warp handles its 32-r half) ----
    for (int rt = 0; rt < 5; rt++) {
        int r0 = rt * 64;
        for (int i = t; i < 4096; i += 256) {
            int r = i >> 6, d = i & 63;
            int rg = r0 + r;
            float v = (rg < 257) ? posV[rg*64 + d] : 0.f;
            __nv_bfloat16 hb, lb;
            split_bf(v, hb, lb);
            VH[d*72 + r] = hb;
            VL[d*72 + r] = lb;
        }
        __syncthreads();
#pragma unroll
        for (int c2 = 0; c2 < 2; c2++) {
            int kc = 2*wn + c2;
            int rA = r0 + 16*kc + 2*cc;
            float v00 = (rA     < 257) ? AP[ r_lo   *264 + rA]     : 0.f;
            float v01 = (rA + 1 < 257) ? AP[ r_lo   *264 + rA + 1] : 0.f;
            float v10 = (rA     < 257) ? AP[(r_lo+8)*264 + rA]     : 0.f;
            float v11 = (rA + 1 < 257) ? AP[(r_lo+8)*264 + rA + 1] : 0.f;
            float v20 = (rA + 8 < 257) ? AP[ r_lo   *264 + rA + 8] : 0.f;
            float v21 = (rA + 9 < 257) ? AP[ r_lo   *264 + rA + 9] : 0.f;
            float v30 = (rA + 8 < 257) ? AP[(r_lo+8)*264 + rA + 8] : 0.f;
            float v31 = (rA + 9 < 257) ? AP[(r_lo+8)*264 + rA + 9] : 0.f;
            __nv_bfloat16 h[8], l[8];
            split_bf(v00, h[0], l[0]); split_bf(v01, h[1], l[1]);
            split_bf(v10, h[2], l[2]); split_bf(v11, h[3], l[3]);
            split_bf(v20, h[4], l[4]); split_bf(v21, h[5], l[5]);
            split_bf(v30, h[6], l[6]); split_bf(v31, h[7], l[7]);
            u32 ah0 = pack2(h[0], h[1]), ah1 = pack2(h[2], h[3]);
            u32 ah2 = pack2(h[4], h[5]), ah3 = pack2(h[6], h[7]);
            u32 al0 = pack2(l[0], l[1]), al1 = pack2(l[2], l[3]);
            u32 al2 = pack2(l[4], l[5]), al3 = pack2(l[6], l[7]);
#pragma unroll
            for (int nd = 0; nd < 8; nd++) {
                const __nv_bfloat16* pvh = VH + (8*nd+grp)*72 + 16*kc + 2*cc;
                const __nv_bfloat16* pvl = VL + (8*nd+grp)*72 + 16*kc + 2*cc;
                u32 bh0 = *(const u32*)pvh, bh1 = *(const u32*)(pvh + 8);
                u32 bl0 = *(const u32*)pvl, bl1 = *(const u32*)(pvl + 8);
                mma16816(o[nd], ah0, ah1, ah2, ah3, bh0, bh1);
                mma16816(o[nd], ah0, ah1, ah2, ah3, bl0, bl1);
                mma16816(o[nd], al0, al1, al2, al3, bh0, bh1);
            }
        }
        __syncthreads();
    }

    // ---- combine warp-pair O partials via scratch (QP region is free now) ----
    float* SC = QP;    // 4 wq * 1024 floats
    if (wn == 1) {
#pragma unroll
        for (int nd = 0; nd < 8; nd++)
            *(float4*)&SC[wq*1024 + nd*128 + lane*4] = *(float4*)&o[nd][0];
    }
    __syncthreads();
    if (wn == 0) {
#pragma unroll
        for (int nd = 0; nd < 8; nd++) {
            float4 p = *(float4*)&SC[wq*1024 + nd*128 + lane*4];
            int d = hh*64 + 8*nd + 2*cc;
            float2 s0 = make_float2((o[nd][0] + p.x) * inv0, (o[nd][1] + p.y) * inv0);
            float2 s1 = make_float2((o[nd][2] + p.z) * inv1, (o[nd][3] + p.w) * inv1);
            *(float2*)&g_O[((size_t)bb*1024 + q0 + r_lo    ) * 512 + d] = s0;
            *(float2*)&g_O[((size_t)bb*1024 + q0 + r_lo + 8) * 512 + d] = s1;
        }
    }
}

// ======================= Kernel 3: output GEMM =============================
__global__ __launch_bounds__(256, 2)
void out_gemm_kernel(const float* __restrict__ Wv,
                     const float* __restrict__ bias,
                     float* __restrict__ C)
{
    __shared__ float As[16][132];
    __shared__ float Bs[16][132];
    const int t  = threadIdx.x;
    const int tx = t & 15, ty = t >> 4;
    const int n0 = blockIdx.x * 128;
    const int m0 = blockIdx.y * 128;

    float acc[8][8];
#pragma unroll
    for (int i = 0; i < 8; i++)
#pragma unroll
        for (int j = 0; j < 8; j++) acc[i][j] = 0.f;

    for (int k0 = 0; k0 < 512; k0 += 16) {
        __syncthreads();
#pragma unroll
        for (int c = 0; c < 2; c++) {
            int i0 = t + c * 256;
            int m = i0 >> 2, kv = i0 & 3;
            float4 v = *(const float4*)(g_O + (size_t)(m0 + m) * 512 + k0 + kv * 4);
            As[kv * 4 + 0][m] = v.x; As[kv * 4 + 1][m] = v.y;
            As[kv * 4 + 2][m] = v.z; As[kv * 4 + 3][m] = v.w;
        }
#pragma unroll
        for (int c = 0; c < 2; c++) {
            int i0 = t + c * 256;
            int k = i0 >> 5, nv = i0 & 31;
            *(float4*)&Bs[k][nv * 4] =
                *(const float4*)(Wv + (size_t)(k0 + k) * 512 + n0 + nv * 4);
        }
        __syncthreads();
#pragma unroll
        for (int kk = 0; kk < 16; kk++) {
            float a_[8], b_[8];
            *(float4*)&a_[0] = *(float4*)&As[kk][ty * 8];
            *(float4*)&a_[4] = *(float4*)&As[kk][ty * 8 + 4];
            *(float4*)&b_[0] = *(float4*)&Bs[kk][tx * 8];
            *(float4*)&b_[4] = *(float4*)&Bs[kk][tx * 8 + 4];
#pragma unroll
            for (int i = 0; i < 8; i++)
#pragma unroll
                for (int j = 0; j < 8; j++)
                    acc[i][j] += a_[i] * b_[j];
        }
    }

#pragma unroll
    for (int i = 0; i < 8; i++) {
        int m = m0 + ty * 8 + i;
#pragma unroll
        for (int jj = 0; jj < 2; jj++) {
            int n = n0 + tx * 8 + jj * 4;
            float4 v;
            v.x = acc[i][jj * 4 + 0] + bias[n + 0];
            v.y = acc[i][jj * 4 + 1] + bias[n + 1];
            v.z = acc[i][jj * 4 + 2] + bias[n + 2];
            v.w = acc[i][jj * 4 + 3] + bias[n + 3];
            *(float4*)(C + (size_t)m * 512 + n) = v;
        }
    }
}

// ============================== launcher ===================================
extern "C" void kernel_launch(void* const* d_in, const int* in_sizes, int n_in,
                              void* d_out, int out_size)
{
    const float* x     = (const float*)d_in[0];
    const int*   mask  = (const int*)  d_in[1];
    const float* W_in  = (const float*)d_in[2];
    const float* b_in  = (const float*)d_in[3];
    const float* W_out = (const float*)d_in[4];
    const float* b_out = (const float*)d_in[5];
    const float* posK  = (const float*)d_in[6];
    const float* posV  = (const float*)d_in[7];
    float* out = (float*)d_out;
    (void)in_sizes; (void)n_in; (void)out_size;

    cudaFuncSetAttribute(attn_kernel,
                         cudaFuncAttributeMaxDynamicSharedMemorySize,
                         ATTN_SMEM);

    qkv_gemm_kernel<<<dim3(12, 64), 256>>>(x, W_in, b_in);
    vtrans_kernel<<<dim3(16, 64), 256>>>();
    attn_kernel<<<dim3(16, 64), 256, ATTN_SMEM>>>(mask, posK, posV);
    out_gemm_kernel<<<dim3(4, 64), 256>>>(W_out, b_out, out);
}